// round 12
// baseline (speedup 1.0000x reference)
#include <cuda_runtime.h>
#include <cuda_bf16.h>
#include <cstdint>

// PWC-Net 9x9 correlation + LeakyReLU(0.1), fp32.
// feat1, feat2: [8, 256, 80, 160]; out: [8, 81, 80, 160]
// out[n, dy*9+dx, y, x] = leaky( (1/256) * sum_c f1[n,c,y,x] * f2pad[n,c,y+dy,x+dx] )
//
// Block: 32x16 pixel tile, one batch n, one dy-group g (3 dy, 27 out channels).
// f1 in registers; f2 double-buffered in smem via cp.async zfill, 1-chunk prefetch.
// R6: row-based fill (fewer regs), f1 preload split, launch_bounds(128,3) -> 12 warps/SM.

#define NN 8
#define CC 256
#define HH 80
#define WW 160
#define HW (HH * WW)
#define KC 8                     // channels per chunk
#define NCHUNK (CC / KC)         // 32
#define TY 16
#define NDY 3
#define F2ROWS (TY + NDY - 1)    // 18
#define F2PITCH 40               // 32 + 8 halo (floats)
#define NROWS (KC * F2ROWS)      // 144 fill rows per chunk
#define BUFWORDS (NROWS * F2PITCH)         // 5760 floats = 23040 B per buffer
#define BUFBYTES (BUFWORDS * 4)

__device__ __forceinline__ void cp_async16(uint32_t dst, const float* src, int src_size) {
    asm volatile("cp.async.cg.shared.global [%0], [%1], 16, %2;\n"
                 :: "r"(dst), "l"(src), "r"(src_size));
}

__global__ __launch_bounds__(128, 3)
void corr_kernel(const float* __restrict__ f1,
                 const float* __restrict__ f2,
                 float* __restrict__ out)
{
    __shared__ float f2s[2 * BUFWORDS];   // 46 KB, double-buffered

    const int tx = threadIdx.x;            // 0..7
    const int ty = threadIdx.y;            // 0..15
    const int t  = ty * 8 + tx;

    const int x0 = blockIdx.x * 32;
    const int g  = blockIdx.y % 3;
    const int y0 = (blockIdx.y / 3) * TY;
    const int n  = blockIdx.z;

    const float* f1n = f1 + (size_t)n * CC * HW;
    const float* f2n = f2 + (size_t)n * CC * HW;

    const int y  = y0 + ty;
    const int xb = x0 + tx * 4;
    const int ybase = y0 + 3 * g - 4;      // global f2 row for smem r=0

    // ---- per-thread fill rows: row0 = t (all), row1 = 128 + t (t < 16)
    // dst word offset = row * F2PITCH; src needs (c, gy) from row = c*18 + r.
    const uint32_t smem_base = (uint32_t)__cvta_generic_to_shared(f2s);
    const int lo = (x0 == 0)   ? 1 : 0;    // first in-bounds i4 slot
    const int hi = (x0 == 128) ? 9 : 10;   // one past last in-bounds i4 slot

    const int c0  = t / F2ROWS;
    const int r0  = t - c0 * F2ROWS;
    const int gy0 = ybase + r0;
    const bool ok0 = (gy0 >= 0 && gy0 < HH);
    const float* src0 = f2n + ((size_t)c0 * HH + (ok0 ? gy0 : 0)) * WW + x0 - 4;
    const uint32_t dst0 = smem_base + (uint32_t)t * (F2PITCH * 4);

    const int t1  = t + 128;
    const int c1  = t1 / F2ROWS;
    const int r1  = t1 - c1 * F2ROWS;
    const int gy1 = ybase + r1;
    const bool ok1 = (gy1 >= 0 && gy1 < HH) && (t < NROWS - 128);
    const float* src1 = f2n + ((size_t)c1 * HH + ((gy1 >= 0 && gy1 < HH) ? gy1 : 0)) * WW + x0 - 4;
    const uint32_t dst1 = smem_base + (uint32_t)t1 * (F2PITCH * 4);

    // ---- accumulators
    float acc[NDY][4][9];
    #pragma unroll
    for (int q = 0; q < NDY; q++)
        #pragma unroll
        for (int px = 0; px < 4; px++)
            #pragma unroll
            for (int dx = 0; dx < 9; dx++)
                acc[q][px][dx] = 0.0f;

    // ---- prologue: fill buffer 0 with chunk 0
    #pragma unroll
    for (int i4 = 0; i4 < 10; i4++) {
        bool in = ok0 && i4 >= lo && i4 < hi;
        cp_async16(dst0 + i4 * 16, in ? (src0 + i4 * 4) : f2n, in ? 16 : 0);
    }
    if (t < NROWS - 128) {
        #pragma unroll
        for (int i4 = 0; i4 < 10; i4++) {
            bool in = ok1 && i4 >= lo && i4 < hi;
            cp_async16(dst1 + i4 * 16, in ? (src1 + i4 * 4) : f2n, in ? 16 : 0);
        }
    }
    asm volatile("cp.async.commit_group;\n" ::);

    const float* f1p = f1n + (size_t)y * WW + xb;   // advances by KC*HW per chunk

    for (int i = 0; i < NCHUNK; i++) {
        const int b = i & 1;
        const uint32_t bufbyte = (uint32_t)(b ^ 1) * BUFBYTES;
        const int boff = b * BUFWORDS;

        __syncthreads();   // all warps done computing on buffer (b^1) from iter i-1

        if (i + 1 < NCHUNK) {
            const size_t choff = (size_t)(i + 1) * KC * HW;
            const float* s0 = src0 + choff;
            #pragma unroll
            for (int i4 = 0; i4 < 10; i4++) {
                bool in = ok0 && i4 >= lo && i4 < hi;
                cp_async16(dst0 + bufbyte + i4 * 16, in ? (s0 + i4 * 4) : f2n, in ? 16 : 0);
            }
            if (t < NROWS - 128) {
                const float* s1 = src1 + choff;
                #pragma unroll
                for (int i4 = 0; i4 < 10; i4++) {
                    bool in = ok1 && i4 >= lo && i4 < hi;
                    cp_async16(dst1 + bufbyte + i4 * 16, in ? (s1 + i4 * 4) : f2n, in ? 16 : 0);
                }
            }
            asm volatile("cp.async.commit_group;\n" ::);
            asm volatile("cp.async.wait_group 1;\n" ::);  // chunk i (buffer b) done
        } else {
            asm volatile("cp.async.wait_group 0;\n" ::);
        }

        __syncthreads();   // all threads' fills of buffer b visible

        // compute in two half-chunks of 4 channels (16 live f1 regs instead of 32)
        #pragma unroll
        for (int cg = 0; cg < 2; cg++) {
            float4 a[4];
            #pragma unroll
            for (int c = 0; c < 4; c++)
                a[c] = *(const float4*)(f1p + (size_t)(cg * 4 + c) * HW);

            #pragma unroll
            for (int c = 0; c < 4; c++) {
                const int cc = cg * 4 + c;
                const float av[4] = {a[c].x, a[c].y, a[c].z, a[c].w};
                #pragma unroll
                for (int q = 0; q < NDY; q++) {
                    const float* wr = &f2s[boff + (cc * F2ROWS + ty + q) * F2PITCH + tx * 4];
                    const float4 w0 = *(const float4*)(wr);
                    const float4 w1 = *(const float4*)(wr + 4);
                    const float4 w2 = *(const float4*)(wr + 8);
                    const float w[12] = {w0.x, w0.y, w0.z, w0.w,
                                         w1.x, w1.y, w1.z, w1.w,
                                         w2.x, w2.y, w2.z, w2.w};
                    #pragma unroll
                    for (int px = 0; px < 4; px++)
                        #pragma unroll
                        for (int dx = 0; dx < 9; dx++)
                            acc[q][px][dx] = fmaf(av[px], w[px + dx], acc[q][px][dx]);
                }
            }
        }

        f1p += (size_t)KC * HW;
    }

    // ---- epilogue: 27 output channels, float4 over px
    const float inv_c = 1.0f / 256.0f;
    #pragma unroll
    for (int q = 0; q < NDY; q++) {
        const int dy = 3 * g + q;
        #pragma unroll
        for (int dx = 0; dx < 9; dx++) {
            const int d = dy * 9 + dx;
            float4 v;
            float s;
            s = acc[q][0][dx] * inv_c; v.x = (s > 0.f) ? s : 0.1f * s;
            s = acc[q][1][dx] * inv_c; v.y = (s > 0.f) ? s : 0.1f * s;
            s = acc[q][2][dx] * inv_c; v.z = (s > 0.f) ? s : 0.1f * s;
            s = acc[q][3][dx] * inv_c; v.w = (s > 0.f) ? s : 0.1f * s;
            *(float4*)(out + (((size_t)n * 81 + d) * HH + y) * WW + xb) = v;
        }
    }
}

extern "C" void kernel_launch(void* const* d_in, const int* in_sizes, int n_in,
                              void* d_out, int out_size)
{
    const float* feat1 = (const float*)d_in[0];
    const float* feat2 = (const float*)d_in[1];
    float* out = (float*)d_out;

    dim3 block(8, 16, 1);                  // 128 threads
    dim3 grid(WW / 32, (HH / TY) * 3, NN); // (5, 15, 8) = 600 blocks
    corr_kernel<<<grid, block>>>(feat1, feat2, out);
}

// round 15
// speedup vs baseline: 2.1791x; 2.1791x over previous
#include <cuda_runtime.h>
#include <cuda_bf16.h>
#include <cstdint>

// PWC-Net 9x9 correlation + LeakyReLU(0.1), fp32.
// feat1, feat2: [8, 256, 80, 160]; out: [8, 81, 80, 160]
// out[n, dy*9+dx, y, x] = leaky( (1/256) * sum_c f1[n,c,y,x] * f2pad[n,c,y+dy,x+dx] )
//
// Block: 32x16 pixel tile, one batch n, one dy-group g (3 dy, 27 out channels).
// f1 in registers; f2 double-buffered in DYNAMIC smem via cp.async zfill, 1-chunk
// prefetch. R13: revert launch_bounds (R6 regression: reg squeeze destroyed codegen);
// KC=16 halves barrier count (32 syncs) and fill-group overhead vs KC=8.

#define NN 8
#define CC 256
#define HH 80
#define WW 160
#define HW (HH * WW)
#define KC 16                    // channels per chunk
#define NCHUNK (CC / KC)         // 16
#define TY 16
#define NDY 3
#define F2ROWS (TY + NDY - 1)    // 18
#define F2PITCH 40               // 32 + 8 halo (floats)
#define NROWS (KC * F2ROWS)      // 288 fill rows per chunk
#define BUFWORDS (NROWS * F2PITCH)   // 11520 floats = 46080 B per buffer
#define BUFBYTES (BUFWORDS * 4)
#define SMEM_TOTAL (2 * BUFBYTES)    // 92160 B (dynamic)

__device__ __forceinline__ void cp_async16(uint32_t dst, const float* src, int src_size) {
    asm volatile("cp.async.cg.shared.global [%0], [%1], 16, %2;\n"
                 :: "r"(dst), "l"(src), "r"(src_size));
}

__global__ void corr_kernel(const float* __restrict__ f1,
                            const float* __restrict__ f2,
                            float* __restrict__ out)
{
    extern __shared__ float f2s[];        // 2 * 45 KB, double-buffered

    const int tx = threadIdx.x;            // 0..7
    const int ty = threadIdx.y;            // 0..15
    const int t  = ty * 8 + tx;

    const int x0 = blockIdx.x * 32;
    const int g  = blockIdx.y % 3;
    const int y0 = (blockIdx.y / 3) * TY;
    const int n  = blockIdx.z;

    const float* f1n = f1 + (size_t)n * CC * HW;
    const float* f2n = f2 + (size_t)n * CC * HW;

    const int y  = y0 + ty;
    const int xb = x0 + tx * 4;
    const int ybase = y0 + 3 * g - 4;      // global f2 row for smem r=0

    // ---- per-thread fill rows: row0 = t, row1 = t+128 (all), row2 = t+256 (t<32)
    // row -> (c = row/18, r = row%18); dst word offset = row * F2PITCH.
    const uint32_t smem_base = (uint32_t)__cvta_generic_to_shared(f2s);
    const int lo = (x0 == 0)   ? 1 : 0;    // first in-bounds i4 slot
    const int hi = (x0 == 128) ? 9 : 10;   // one past last in-bounds i4 slot

    const int c0  = t / F2ROWS;
    const int r0  = t - c0 * F2ROWS;
    const int gy0 = ybase + r0;
    const bool ok0 = (gy0 >= 0 && gy0 < HH);
    const float* src0 = f2n + ((size_t)c0 * HH + (ok0 ? gy0 : 0)) * WW + x0 - 4;
    const uint32_t dst0 = smem_base + (uint32_t)t * (F2PITCH * 4);

    const int row1 = t + 128;
    const int c1  = row1 / F2ROWS;
    const int r1  = row1 - c1 * F2ROWS;
    const int gy1 = ybase + r1;
    const bool ok1 = (gy1 >= 0 && gy1 < HH);
    const float* src1 = f2n + ((size_t)c1 * HH + (ok1 ? gy1 : 0)) * WW + x0 - 4;
    const uint32_t dst1 = smem_base + (uint32_t)row1 * (F2PITCH * 4);

    const int row2 = t + 256;
    const int c2  = row2 / F2ROWS;
    const int r2  = row2 - c2 * F2ROWS;
    const int gy2 = ybase + r2;
    const bool has2 = (t < NROWS - 256);   // t < 32
    const bool ok2 = has2 && (gy2 >= 0 && gy2 < HH);
    const float* src2 = f2n + ((size_t)c2 * HH + ((gy2 >= 0 && gy2 < HH) ? gy2 : 0)) * WW + x0 - 4;
    const uint32_t dst2 = smem_base + (uint32_t)row2 * (F2PITCH * 4);

    // ---- accumulators
    float acc[NDY][4][9];
    #pragma unroll
    for (int q = 0; q < NDY; q++)
        #pragma unroll
        for (int px = 0; px < 4; px++)
            #pragma unroll
            for (int dx = 0; dx < 9; dx++)
                acc[q][px][dx] = 0.0f;

    // ---- prologue: fill buffer 0 with chunk 0
    #pragma unroll
    for (int i4 = 0; i4 < 10; i4++) {
        bool in0 = ok0 && i4 >= lo && i4 < hi;
        cp_async16(dst0 + i4 * 16, in0 ? (src0 + i4 * 4) : f2n, in0 ? 16 : 0);
        bool in1 = ok1 && i4 >= lo && i4 < hi;
        cp_async16(dst1 + i4 * 16, in1 ? (src1 + i4 * 4) : f2n, in1 ? 16 : 0);
    }
    if (has2) {
        #pragma unroll
        for (int i4 = 0; i4 < 10; i4++) {
            bool in2 = ok2 && i4 >= lo && i4 < hi;
            cp_async16(dst2 + i4 * 16, in2 ? (src2 + i4 * 4) : f2n, in2 ? 16 : 0);
        }
    }
    asm volatile("cp.async.commit_group;\n" ::);

    const float* f1p = f1n + (size_t)y * WW + xb;   // advances by KC*HW per chunk

    for (int i = 0; i < NCHUNK; i++) {
        const int b = i & 1;
        const uint32_t bufbyte = (uint32_t)(b ^ 1) * BUFBYTES;
        const int boff = b * BUFWORDS;

        __syncthreads();   // all warps done computing on buffer (b^1) from iter i-1

        if (i + 1 < NCHUNK) {
            const size_t choff = (size_t)(i + 1) * KC * HW;
            const float* s0 = src0 + choff;
            const float* s1 = src1 + choff;
            #pragma unroll
            for (int i4 = 0; i4 < 10; i4++) {
                bool in0 = ok0 && i4 >= lo && i4 < hi;
                cp_async16(dst0 + bufbyte + i4 * 16, in0 ? (s0 + i4 * 4) : f2n, in0 ? 16 : 0);
                bool in1 = ok1 && i4 >= lo && i4 < hi;
                cp_async16(dst1 + bufbyte + i4 * 16, in1 ? (s1 + i4 * 4) : f2n, in1 ? 16 : 0);
            }
            if (has2) {
                const float* s2 = src2 + choff;
                #pragma unroll
                for (int i4 = 0; i4 < 10; i4++) {
                    bool in2 = ok2 && i4 >= lo && i4 < hi;
                    cp_async16(dst2 + bufbyte + i4 * 16, in2 ? (s2 + i4 * 4) : f2n, in2 ? 16 : 0);
                }
            }
            asm volatile("cp.async.commit_group;\n" ::);
            asm volatile("cp.async.wait_group 1;\n" ::);  // chunk i (buffer b) done
        } else {
            asm volatile("cp.async.wait_group 0;\n" ::);
        }

        __syncthreads();   // all threads' fills of buffer b visible

        // compute 16 channels in 4 groups of 4 (16 live f1 regs per group)
        #pragma unroll
        for (int cg = 0; cg < 4; cg++) {
            float4 a[4];
            #pragma unroll
            for (int c = 0; c < 4; c++)
                a[c] = *(const float4*)(f1p + (size_t)(cg * 4 + c) * HW);

            #pragma unroll
            for (int c = 0; c < 4; c++) {
                const int cc = cg * 4 + c;
                const float av[4] = {a[c].x, a[c].y, a[c].z, a[c].w};
                #pragma unroll
                for (int q = 0; q < NDY; q++) {
                    const float* wr = &f2s[boff + (cc * F2ROWS + ty + q) * F2PITCH + tx * 4];
                    const float4 w0 = *(const float4*)(wr);
                    const float4 w1 = *(const float4*)(wr + 4);
                    const float4 w2 = *(const float4*)(wr + 8);
                    const float w[12] = {w0.x, w0.y, w0.z, w0.w,
                                         w1.x, w1.y, w1.z, w1.w,
                                         w2.x, w2.y, w2.z, w2.w};
                    #pragma unroll
                    for (int px = 0; px < 4; px++)
                        #pragma unroll
                        for (int dx = 0; dx < 9; dx++)
                            acc[q][px][dx] = fmaf(av[px], w[px + dx], acc[q][px][dx]);
                }
            }
        }

        f1p += (size_t)KC * HW;
    }

    // ---- epilogue: 27 output channels, float4 over px
    const float inv_c = 1.0f / 256.0f;
    #pragma unroll
    for (int q = 0; q < NDY; q++) {
        const int dy = 3 * g + q;
        #pragma unroll
        for (int dx = 0; dx < 9; dx++) {
            const int d = dy * 9 + dx;
            float4 v;
            float s;
            s = acc[q][0][dx] * inv_c; v.x = (s > 0.f) ? s : 0.1f * s;
            s = acc[q][1][dx] * inv_c; v.y = (s > 0.f) ? s : 0.1f * s;
            s = acc[q][2][dx] * inv_c; v.z = (s > 0.f) ? s : 0.1f * s;
            s = acc[q][3][dx] * inv_c; v.w = (s > 0.f) ? s : 0.1f * s;
            *(float4*)(out + (((size_t)n * 81 + d) * HH + y) * WW + xb) = v;
        }
    }
}

extern "C" void kernel_launch(void* const* d_in, const int* in_sizes, int n_in,
                              void* d_out, int out_size)
{
    const float* feat1 = (const float*)d_in[0];
    const float* feat2 = (const float*)d_in[1];
    float* out = (float*)d_out;

    // >48KB dynamic smem opt-in (idempotent; executes immediately, not captured)
    cudaFuncSetAttribute(corr_kernel,
                         cudaFuncAttributeMaxDynamicSharedMemorySize, SMEM_TOTAL);

    dim3 block(8, 16, 1);                  // 128 threads
    dim3 grid(WW / 32, (HH / TY) * 3, NN); // (5, 15, 8) = 600 blocks
    corr_kernel<<<grid, block, SMEM_TOTAL>>>(feat1, feat2, out);
}